// round 14
// baseline (speedup 1.0000x reference)
#include <cuda_runtime.h>
#include <math.h>

// Problem constants
#define NB   16384
#define ND   256
#define NH   256
#define NO   256
#define NE   32
#define NACT 22

// Scratch (device globals: the sanctioned no-alloc workaround)
__device__ float g_w[NB * NE];                 // gate weights, 2 MB
__device__ float g_h[134217728];               // h[e][b][h] = 32*16384*256 fp32, 512 MB

// ---------------------------------------------------------------------------
// Kernel 1: gate. One warp per token. fp64 accumulation/softmax so the
// top-22 boundary decision is as close to exact as possible (rank flips vs
// the reference are the dominant correctness hazard).
// ---------------------------------------------------------------------------
__global__ void gate_kernel(const float* __restrict__ x,
                            const float* __restrict__ Wg,
                            const float* __restrict__ bg)
{
    const int gw   = (blockIdx.x * blockDim.x + threadIdx.x) >> 5;  // token id
    const int lane = threadIdx.x & 31;                              // expert id
    if (gw >= NB) return;

    const float* xr = x + (size_t)gw * ND;
    float xv[8];
#pragma unroll
    for (int j = 0; j < 8; j++) xv[j] = xr[lane + 32 * j];

    double score = 0.0;
#pragma unroll 1
    for (int e = 0; e < NE; e++) {
        const float* wr = Wg + e * ND;
        double p = 0.0;
#pragma unroll
        for (int j = 0; j < 8; j++)
            p += (double)xv[j] * (double)wr[lane + 32 * j];
#pragma unroll
        for (int off = 16; off > 0; off >>= 1)
            p += __shfl_xor_sync(0xffffffffu, p, off);
        if (e == lane) score = p;
    }
    score = (score + (double)bg[lane]) / 2.718281828459045;  // / TEMP (np.e)

    // softmax over 32 lanes (fp64)
    double m = score;
#pragma unroll
    for (int off = 16; off > 0; off >>= 1) {
        double o = __shfl_xor_sync(0xffffffffu, m, off);
        m = (o > m) ? o : m;
    }
    double pe = exp(score - m);
    double ps = pe;
#pragma unroll
    for (int off = 16; off > 0; off >>= 1)
        ps += __shfl_xor_sync(0xffffffffu, ps, off);
    double prob = pe / ps;

    // rank: number of experts strictly ahead (ties broken by lower index,
    // matching jax.lax.top_k)
    int cnt = 0;
#pragma unroll
    for (int i = 0; i < 32; i++) {
        double pi = __shfl_sync(0xffffffffu, prob, i);
        if (pi > prob || (pi == prob && i < lane)) cnt++;
    }
    double kp = (cnt < NACT) ? prob : 0.0;
    double ks = kp;
#pragma unroll
    for (int off = 16; off > 0; off >>= 1)
        ks += __shfl_xor_sync(0xffffffffu, ks, off);

    g_w[gw * NE + lane] = (float)(kp / (ks + 1e-8));
}

// ---------------------------------------------------------------------------
// Kernel 2: h[e,b,:] = relu(x @ W1[e]^T + b1[e]).  Grid (B/128, H/128, E).
// 128x128 tile, BK=16, 256 threads, 8x8 microtile. Both operands K-major
// (K = D); tiles stored transposed in SMEM for conflict-light inner reads.
// ---------------------------------------------------------------------------
__global__ void __launch_bounds__(256, 2)
hidden_kernel(const float* __restrict__ x,
              const float* __restrict__ W1,
              const float* __restrict__ b1)
{
    __shared__ float As[16][128];
    __shared__ float Bs[16][128];

    const int e  = blockIdx.z;
    const int b0 = blockIdx.x * 128;
    const int h0 = blockIdx.y * 128;
    const int tid = threadIdx.x;
    const int tx = tid & 15;
    const int ty = tid >> 4;
    const int lr = tid >> 2;            // 0..63
    const int lc = (tid & 3) << 2;      // 0,4,8,12

    const float* Ab = x  + (size_t)b0 * ND;
    const float* Bb = W1 + ((size_t)e * NH + h0) * ND;

    float acc[8][8];
#pragma unroll
    for (int i = 0; i < 8; i++)
#pragma unroll
        for (int j = 0; j < 8; j++) acc[i][j] = 0.f;

    for (int k0 = 0; k0 < ND; k0 += 16) {
#pragma unroll
        for (int p = 0; p < 2; p++) {
            int r = p * 64 + lr;
            float4 va = *reinterpret_cast<const float4*>(Ab + (size_t)r * ND + k0 + lc);
            As[lc + 0][r] = va.x; As[lc + 1][r] = va.y;
            As[lc + 2][r] = va.z; As[lc + 3][r] = va.w;
            float4 vb = *reinterpret_cast<const float4*>(Bb + (size_t)r * ND + k0 + lc);
            Bs[lc + 0][r] = vb.x; Bs[lc + 1][r] = vb.y;
            Bs[lc + 2][r] = vb.z; Bs[lc + 3][r] = vb.w;
        }
        __syncthreads();
#pragma unroll
        for (int kk = 0; kk < 16; kk++) {
            float a[8], b[8];
            float4 a0 = *reinterpret_cast<const float4*>(&As[kk][ty * 8]);
            float4 a1 = *reinterpret_cast<const float4*>(&As[kk][ty * 8 + 4]);
            float4 c0 = *reinterpret_cast<const float4*>(&Bs[kk][tx * 8]);
            float4 c1 = *reinterpret_cast<const float4*>(&Bs[kk][tx * 8 + 4]);
            a[0]=a0.x; a[1]=a0.y; a[2]=a0.z; a[3]=a0.w;
            a[4]=a1.x; a[5]=a1.y; a[6]=a1.z; a[7]=a1.w;
            b[0]=c0.x; b[1]=c0.y; b[2]=c0.z; b[3]=c0.w;
            b[4]=c1.x; b[5]=c1.y; b[6]=c1.z; b[7]=c1.w;
#pragma unroll
            for (int i = 0; i < 8; i++)
#pragma unroll
                for (int j = 0; j < 8; j++)
                    acc[i][j] += a[i] * b[j];
        }
        __syncthreads();
    }

    // epilogue: + b1, relu, store to g_h[e][b][h]
    float bias[8];
    const float* brow = b1 + e * NH + h0 + tx * 8;
#pragma unroll
    for (int j = 0; j < 8; j++) bias[j] = brow[j];

    float* hp = g_h + ((size_t)e * NB + b0) * NH + h0 + tx * 8;
#pragma unroll
    for (int i = 0; i < 8; i++) {
        int mrow = ty * 8 + i;
        float4 o0, o1;
        o0.x = fmaxf(acc[i][0] + bias[0], 0.f);
        o0.y = fmaxf(acc[i][1] + bias[1], 0.f);
        o0.z = fmaxf(acc[i][2] + bias[2], 0.f);
        o0.w = fmaxf(acc[i][3] + bias[3], 0.f);
        o1.x = fmaxf(acc[i][4] + bias[4], 0.f);
        o1.y = fmaxf(acc[i][5] + bias[5], 0.f);
        o1.z = fmaxf(acc[i][6] + bias[6], 0.f);
        o1.w = fmaxf(acc[i][7] + bias[7], 0.f);
        *reinterpret_cast<float4*>(hp + (size_t)mrow * NH)     = o0;
        *reinterpret_cast<float4*>(hp + (size_t)mrow * NH + 4) = o1;
    }
}

// ---------------------------------------------------------------------------
// Kernel 3: out[b,o] = sum_e w[b,e] * (h[e,b,:] @ W2[e]^T) + sum_e w[b,e]*b2[e,o]
// Grid (B/64, O/128). 64x128 tile, BK=16, 256 threads, 4x8 microtile.
// w[b,e] is folded into the A fragment at SMEM-load time; the b2 term is a
// tiny rank-32 FMA in the epilogue.
// ---------------------------------------------------------------------------
__global__ void __launch_bounds__(256)
combine_kernel(const float* __restrict__ W2,
               const float* __restrict__ b2,
               float* __restrict__ out)
{
    __shared__ float As[16][64];
    __shared__ float Bs[16][128];
    __shared__ float sw[64 * 33];       // padded: bank-conflict-free column reads
    __shared__ float b2s[32][128];

    const int b0 = blockIdx.x * 64;
    const int o0 = blockIdx.y * 128;
    const int tid = threadIdx.x;
    const int tx = tid & 15;
    const int ty = tid >> 4;
    const int lr = tid >> 2;            // 0..63
    const int lc = (tid & 3) << 2;      // 0,4,8,12

    // stage gate weights [64 tokens x 32 experts] and b2 tile [32 x 128]
#pragma unroll
    for (int i = 0; i < 8; i++) {
        int idx = tid + 256 * i;                 // 0..2047
        int r = idx >> 5, e = idx & 31;
        sw[r * 33 + e] = g_w[(size_t)(b0 + r) * NE + e];
    }
#pragma unroll
    for (int i = 0; i < 16; i++) {
        int idx = tid + 256 * i;                 // 0..4095
        int e = idx >> 7, oo = idx & 127;
        b2s[e][oo] = b2[e * NO + o0 + oo];
    }
    __syncthreads();

    float acc[4][8];
#pragma unroll
    for (int i = 0; i < 4; i++)
#pragma unroll
        for (int j = 0; j < 8; j++) acc[i][j] = 0.f;

#pragma unroll 1
    for (int e = 0; e < NE; e++) {
        const float* Ab = g_h + ((size_t)e * NB + b0) * NH;
        const float* Bb = W2  + ((size_t)e * NO + o0) * NH;
        for (int k0 = 0; k0 < NH; k0 += 16) {
            {   // A tile: 64 rows, scaled by per-token gate weight
                float wv = sw[lr * 33 + e];
                float4 va = *reinterpret_cast<const float4*>(Ab + (size_t)lr * NH + k0 + lc);
                As[lc + 0][lr] = va.x * wv; As[lc + 1][lr] = va.y * wv;
                As[lc + 2][lr] = va.z * wv; As[lc + 3][lr] = va.w * wv;
            }
#pragma unroll
            for (int p = 0; p < 2; p++) {        // B tile: 128 rows
                int r = p * 64 + lr;
                float4 vb = *reinterpret_cast<const float4*>(Bb + (size_t)r * NH + k0 + lc);
                Bs[lc + 0][r] = vb.x; Bs[lc + 1][r] = vb.y;
                Bs[lc + 2][r] = vb.z; Bs[lc + 3][r] = vb.w;
            }
            __syncthreads();
#pragma unroll
            for (int kk = 0; kk < 16; kk++) {
                float a[4], b[8];
                float4 av = *reinterpret_cast<const float4*>(&As[kk][ty * 4]);
                float4 c0 = *reinterpret_cast<const float4*>(&Bs[kk][tx * 8]);
                float4 c1 = *reinterpret_cast<const float4*>(&Bs[kk][tx * 8 + 4]);
                a[0]=av.x; a[1]=av.y; a[2]=av.z; a[3]=av.w;
                b[0]=c0.x; b[1]=c0.y; b[2]=c0.z; b[3]=c0.w;
                b[4]=c1.x; b[5]=c1.y; b[6]=c1.z; b[7]=c1.w;
#pragma unroll
                for (int i = 0; i < 4; i++)
#pragma unroll
                    for (int j = 0; j < 8; j++)
                        acc[i][j] += a[i] * b[j];
            }
            __syncthreads();
        }
    }

    // epilogue: + sum_e w[b,e] * b2[e,o]
#pragma unroll 1
    for (int e = 0; e < NE; e++) {
        float bv[8];
#pragma unroll
        for (int j = 0; j < 8; j++) bv[j] = b2s[e][tx * 8 + j];
#pragma unroll
        for (int i = 0; i < 4; i++) {
            float wv = sw[(ty * 4 + i) * 33 + e];
#pragma unroll
            for (int j = 0; j < 8; j++) acc[i][j] += wv * bv[j];
        }
    }

    // store
#pragma unroll
    for (int i = 0; i < 4; i++) {
        int mrow = ty * 4 + i;
        float* op = out + (size_t)(b0 + mrow) * NO + o0 + tx * 8;
        float4 o0v, o1v;
        o0v.x = acc[i][0]; o0v.y = acc[i][1]; o0v.z = acc[i][2]; o0v.w = acc[i][3];
        o1v.x = acc[i][4]; o1v.y = acc[i][5]; o1v.z = acc[i][6]; o1v.w = acc[i][7];
        *reinterpret_cast<float4*>(op)     = o0v;
        *reinterpret_cast<float4*>(op + 4) = o1v;
    }
}

// ---------------------------------------------------------------------------
extern "C" void kernel_launch(void* const* d_in, const int* in_sizes, int n_in,
                              void* d_out, int out_size) {
    (void)in_sizes; (void)n_in; (void)out_size;
    const float* x  = (const float*)d_in[0];
    const float* W1 = (const float*)d_in[1];
    const float* b1 = (const float*)d_in[2];
    const float* W2 = (const float*)d_in[3];
    const float* b2 = (const float*)d_in[4];
    const float* Wg = (const float*)d_in[5];
    const float* bg = (const float*)d_in[6];
    float* out = (float*)d_out;

    gate_kernel<<<NB / 8, 256>>>(x, Wg, bg);                    // 8 tokens/block
    hidden_kernel<<<dim3(NB / 128, NH / 128, NE), 256>>>(x, W1, b1);
    combine_kernel<<<dim3(NB / 64, NO / 128), 256>>>(W2, b2, out);
}

// round 15
// speedup vs baseline: 1.0199x; 1.0199x over previous
#include <cuda_runtime.h>
#include <math.h>

// Problem constants
#define NB   16384
#define ND   256
#define NH   256
#define NO   256
#define NE   32
#define NACT 22

// Scratch (device globals: the sanctioned no-alloc workaround)
__device__ float g_w[NB * NE];                 // gate weights, 2 MB
__device__ float g_h[134217728];               // h[e][b][h] = 32*16384*256 fp32, 512 MB

// ---------------------------------------------------------------------------
// Packed f32x2 helpers (Blackwell FFMA2: 2 fp32 FMAs per instruction).
// Rounding identical to scalar fmaf, so numerics are unchanged.
// ---------------------------------------------------------------------------
__device__ __forceinline__ unsigned long long pk2(float a, float b) {
    unsigned long long r;
    asm("mov.b64 %0, {%1,%2};" : "=l"(r) : "f"(a), "f"(b));
    return r;
}
__device__ __forceinline__ void fma2(unsigned long long& d,
                                     unsigned long long a, unsigned long long b) {
    asm("fma.rn.f32x2 %0, %1, %2, %0;" : "+l"(d) : "l"(a), "l"(b));
}
__device__ __forceinline__ float2 up2(unsigned long long v) {
    float lo, hi;
    asm("mov.b64 {%0,%1}, %2;" : "=f"(lo), "=f"(hi) : "l"(v));
    float2 r; r.x = lo; r.y = hi; return r;
}

// ---------------------------------------------------------------------------
// Kernel 1: gate. One warp per token, lane = expert. All hot-loop math is a
// straight fp64 FMA chain over SMEM (no shuffles until the final reductions),
// so it is throughput-bound on the fp64 pipe instead of shfl latency.
// Ranking uses raw scores (softmax is monotone -> identical top-k ordering).
// ---------------------------------------------------------------------------
__global__ void __launch_bounds__(128)
gate_kernel(const float* __restrict__ x,
            const float* __restrict__ Wg,
            const float* __restrict__ bg)
{
    __shared__ float  wgt[256 * 33];     // Wg^T, padded: wgt[d*33+e]
    __shared__ double xs[4][256];        // 4 tokens' x rows in fp64
    __shared__ double bgs[32];

    const int tid  = threadIdx.x;
    const int lane = tid & 31;           // expert id
    const int w    = tid >> 5;           // warp id = token slot
    const int tok  = blockIdx.x * 4 + w;

    // Stage Wg transposed: coalesced gmem read, conflict-free smem write
    for (int idx = tid; idx < NE * ND; idx += 128) {
        int d = idx & 255, e = idx >> 8;
        wgt[d * 33 + e] = Wg[e * ND + d];
    }
    if (tid < 32) bgs[tid] = (double)bg[tid];
    const float* xr = x + (size_t)tok * ND;
    for (int j = lane; j < ND; j += 32) xs[w][j] = (double)xr[j];
    __syncthreads();

    // score[e] = sum_d x[d] * Wg[e][d]  (fp64 accumulate)
    double acc = 0.0;
#pragma unroll 8
    for (int d = 0; d < ND; d++)
        acc += xs[w][d] * (double)wgt[d * 33 + lane];

    double score = (acc + bgs[lane]) / 2.718281828459045;   // / TEMP (np.e)

    // softmax pieces (fp64)
    double m = score;
#pragma unroll
    for (int off = 16; off > 0; off >>= 1) {
        double o = __shfl_xor_sync(0xffffffffu, m, off);
        if (o > m) m = o;
    }
    double ex = exp(score - m);
    double Z = ex;
#pragma unroll
    for (int off = 16; off > 0; off >>= 1)
        Z += __shfl_xor_sync(0xffffffffu, Z, off);

    // rank by score (monotone w.r.t. prob); ties -> lower index first,
    // matching jax.lax.top_k
    int cnt = 0;
#pragma unroll
    for (int i = 0; i < 32; i++) {
        double si = __shfl_sync(0xffffffffu, score, i);
        if (si > score || (si == score && i < lane)) cnt++;
    }
    double prob = ex / Z;
    double kp = (cnt < NACT) ? prob : 0.0;
    double S = kp;
#pragma unroll
    for (int off = 16; off > 0; off >>= 1)
        S += __shfl_xor_sync(0xffffffffu, S, off);

    g_w[(size_t)tok * NE + lane] = (float)(kp / (S + 1e-8));
}

// ---------------------------------------------------------------------------
// Kernel 2: h[e,b,:] = relu(x @ W1[e]^T + b1[e]).  Grid (B/128, H/128, E).
// 128x128 tile, BK=16, 256 threads, 8x8 microtile, packed f32x2 FMAs.
// ---------------------------------------------------------------------------
__global__ void __launch_bounds__(256, 2)
hidden_kernel(const float* __restrict__ x,
              const float* __restrict__ W1,
              const float* __restrict__ b1)
{
    __shared__ float As[16][128];
    __shared__ float Bs[16][128];

    const int e  = blockIdx.z;
    const int b0 = blockIdx.x * 128;
    const int h0 = blockIdx.y * 128;
    const int tid = threadIdx.x;
    const int tx = tid & 15;
    const int ty = tid >> 4;
    const int lr = tid >> 2;            // 0..63
    const int lc = (tid & 3) << 2;      // 0,4,8,12

    const float* Ab = x  + (size_t)b0 * ND;
    const float* Bb = W1 + ((size_t)e * NH + h0) * ND;

    unsigned long long acc[8][4];       // packed pairs along the j axis
#pragma unroll
    for (int i = 0; i < 8; i++)
#pragma unroll
        for (int j = 0; j < 4; j++) acc[i][j] = 0ull;

    for (int k0 = 0; k0 < ND; k0 += 16) {
#pragma unroll
        for (int p = 0; p < 2; p++) {
            int r = p * 64 + lr;
            float4 va = *reinterpret_cast<const float4*>(Ab + (size_t)r * ND + k0 + lc);
            As[lc + 0][r] = va.x; As[lc + 1][r] = va.y;
            As[lc + 2][r] = va.z; As[lc + 3][r] = va.w;
            float4 vb = *reinterpret_cast<const float4*>(Bb + (size_t)r * ND + k0 + lc);
            Bs[lc + 0][r] = vb.x; Bs[lc + 1][r] = vb.y;
            Bs[lc + 2][r] = vb.z; Bs[lc + 3][r] = vb.w;
        }
        __syncthreads();
#pragma unroll
        for (int kk = 0; kk < 16; kk++) {
            float a[8];
            float4 a0 = *reinterpret_cast<const float4*>(&As[kk][ty * 8]);
            float4 a1 = *reinterpret_cast<const float4*>(&As[kk][ty * 8 + 4]);
            a[0]=a0.x; a[1]=a0.y; a[2]=a0.z; a[3]=a0.w;
            a[4]=a1.x; a[5]=a1.y; a[6]=a1.z; a[7]=a1.w;
            const unsigned long long* bp =
                reinterpret_cast<const unsigned long long*>(&Bs[kk][tx * 8]);
            unsigned long long bq0 = bp[0], bq1 = bp[1], bq2 = bp[2], bq3 = bp[3];
#pragma unroll
            for (int i = 0; i < 8; i++) {
                unsigned long long av = pk2(a[i], a[i]);
                fma2(acc[i][0], av, bq0);
                fma2(acc[i][1], av, bq1);
                fma2(acc[i][2], av, bq2);
                fma2(acc[i][3], av, bq3);
            }
        }
        __syncthreads();
    }

    // epilogue: + b1, relu, store to g_h[e][b][h]
    float bias[8];
    const float* brow = b1 + e * NH + h0 + tx * 8;
#pragma unroll
    for (int j = 0; j < 8; j++) bias[j] = brow[j];

    float* hp = g_h + ((size_t)e * NB + b0) * NH + h0 + tx * 8;
#pragma unroll
    for (int i = 0; i < 8; i++) {
        int mrow = ty * 8 + i;
        float v[8];
#pragma unroll
        for (int j = 0; j < 4; j++) {
            float2 u = up2(acc[i][j]);
            v[2 * j]     = fmaxf(u.x + bias[2 * j],     0.f);
            v[2 * j + 1] = fmaxf(u.y + bias[2 * j + 1], 0.f);
        }
        float4 o0, o1;
        o0.x=v[0]; o0.y=v[1]; o0.z=v[2]; o0.w=v[3];
        o1.x=v[4]; o1.y=v[5]; o1.z=v[6]; o1.w=v[7];
        *reinterpret_cast<float4*>(hp + (size_t)mrow * NH)     = o0;
        *reinterpret_cast<float4*>(hp + (size_t)mrow * NH + 4) = o1;
    }
}

// ---------------------------------------------------------------------------
// Kernel 3: out[b,o] = sum_e w[b,e]*(h[e,b,:] @ W2[e]^T) + sum_e w[b,e]*b2[e,o]
// Grid (B/64, O/128). 64x128 tile, BK=16, 256 threads, 4x8 microtile,
// packed f32x2 FMAs. Gate weight folded into the A fragment at SMEM load.
// ---------------------------------------------------------------------------
__global__ void __launch_bounds__(256)
combine_kernel(const float* __restrict__ W2,
               const float* __restrict__ b2,
               float* __restrict__ out)
{
    __shared__ float As[16][64];
    __shared__ float Bs[16][128];
    __shared__ float sw[64 * 33];       // padded gate weights
    __shared__ float b2s[32][128];

    const int b0 = blockIdx.x * 64;
    const int o0 = blockIdx.y * 128;
    const int tid = threadIdx.x;
    const int tx = tid & 15;
    const int ty = tid >> 4;
    const int lr = tid >> 2;            // 0..63
    const int lc = (tid & 3) << 2;      // 0,4,8,12

#pragma unroll
    for (int i = 0; i < 8; i++) {
        int idx = tid + 256 * i;
        int r = idx >> 5, e = idx & 31;
        sw[r * 33 + e] = g_w[(size_t)(b0 + r) * NE + e];
    }
#pragma unroll
    for (int i = 0; i < 16; i++) {
        int idx = tid + 256 * i;
        int e = idx >> 7, oo = idx & 127;
        b2s[e][oo] = b2[e * NO + o0 + oo];
    }
    __syncthreads();

    unsigned long long acc[4][4];
#pragma unroll
    for (int i = 0; i < 4; i++)
#pragma unroll
        for (int j = 0; j < 4; j++) acc[i][j] = 0ull;

#pragma unroll 1
    for (int e = 0; e < NE; e++) {
        const float* Ab = g_h + ((size_t)e * NB + b0) * NH;
        const float* Bb = W2  + ((size_t)e * NO + o0) * NH;
        for (int k0 = 0; k0 < NH; k0 += 16) {
            {   // A tile scaled by per-token gate weight
                float wv = sw[lr * 33 + e];
                float4 va = *reinterpret_cast<const float4*>(Ab + (size_t)lr * NH + k0 + lc);
                As[lc + 0][lr] = va.x * wv; As[lc + 1][lr] = va.y * wv;
                As[lc + 2][lr] = va.z * wv; As[lc + 3][lr] = va.w * wv;
            }
#pragma unroll
            for (int p = 0; p < 2; p++) {
                int r = p * 64 + lr;
                float4 vb = *reinterpret_cast<const float4*>(Bb + (size_t)r * NH + k0 + lc);
                Bs[lc + 0][r] = vb.x; Bs[lc + 1][r] = vb.y;
                Bs[lc + 2][r] = vb.z; Bs[lc + 3][r] = vb.w;
            }
            __syncthreads();
#pragma unroll
            for (int kk = 0; kk < 16; kk++) {
                float a[4];
                float4 av4 = *reinterpret_cast<const float4*>(&As[kk][ty * 4]);
                a[0]=av4.x; a[1]=av4.y; a[2]=av4.z; a[3]=av4.w;
                const unsigned long long* bp =
                    reinterpret_cast<const unsigned long long*>(&Bs[kk][tx * 8]);
                unsigned long long bq0 = bp[0], bq1 = bp[1], bq2 = bp[2], bq3 = bp[3];
#pragma unroll
                for (int i = 0; i < 4; i++) {
                    unsigned long long av = pk2(a[i], a[i]);
                    fma2(acc[i][0], av, bq0);
                    fma2(acc[i][1], av, bq1);
                    fma2(acc[i][2], av, bq2);
                    fma2(acc[i][3], av, bq3);
                }
            }
            __syncthreads();
        }
    }

    // unpack + b2 epilogue + store
    float accf[4][8];
#pragma unroll
    for (int i = 0; i < 4; i++)
#pragma unroll
        for (int j = 0; j < 4; j++) {
            float2 u = up2(acc[i][j]);
            accf[i][2 * j] = u.x; accf[i][2 * j + 1] = u.y;
        }

#pragma unroll 1
    for (int e = 0; e < NE; e++) {
        float bv[8];
#pragma unroll
        for (int j = 0; j < 8; j++) bv[j] = b2s[e][tx * 8 + j];
#pragma unroll
        for (int i = 0; i < 4; i++) {
            float wv = sw[(ty * 4 + i) * 33 + e];
#pragma unroll
            for (int j = 0; j < 8; j++) accf[i][j] += wv * bv[j];
        }
    }

#pragma unroll
    for (int i = 0; i < 4; i++) {
        int mrow = ty * 4 + i;
        float* op = out + (size_t)(b0 + mrow) * NO + o0 + tx * 8;
        float4 o0v, o1v;
        o0v.x = accf[i][0]; o0v.y = accf[i][1]; o0v.z = accf[i][2]; o0v.w = accf[i][3];
        o1v.x = accf[i][4]; o1v.y = accf[i][5]; o1v.z = accf[i][6]; o1v.w = accf[i][7];
        *reinterpret_cast<float4*>(op)     = o0v;
        *reinterpret_cast<float4*>(op + 4) = o1v;
    }
}

// ---------------------------------------------------------------------------
extern "C" void kernel_launch(void* const* d_in, const int* in_sizes, int n_in,
                              void* d_out, int out_size) {
    (void)in_sizes; (void)n_in; (void)out_size;
    const float* x  = (const float*)d_in[0];
    const float* W1 = (const float*)d_in[1];
    const float* b1 = (const float*)d_in[2];
    const float* W2 = (const float*)d_in[3];
    const float* b2 = (const float*)d_in[4];
    const float* Wg = (const float*)d_in[5];
    const float* bg = (const float*)d_in[6];
    float* out = (float*)d_out;

    gate_kernel<<<NB / 4, 128>>>(x, Wg, bg);                    // 4 tokens/block
    hidden_kernel<<<dim3(NB / 128, NH / 128, NE), 256>>>(x, W1, b1);
    combine_kernel<<<dim3(NB / 64, NO / 128), 256>>>(W2, b2, out);
}